// round 10
// baseline (speedup 1.0000x reference)
#include <cuda_runtime.h>
#include <cstdint>

#define MM 2048
#define NODE 64
#define TT 256
#define RB 16
#define NTHREADS 256
#define NBUF 8                    // W ring depth (8 x 16KB = 128KB dynamic smem)
#define WBUF_FLOATS 4096          // one W[t]: 64 k-rows x 64 j

// Scratch (no cudaMalloc allowed)
__device__ __align__(16) float WT_g[TT * NODE * NODE];   // transposed W, k-major (4 MB)
__device__ __align__(16) float st_g[TT * NODE];          // softplus table, st_g[0][:]=1

// ---------------- phase 0a: W[t][j][k] -> WT[t][k][j] ----------------
__global__ void k_transpose_W(const float* __restrict__ W) {
    __shared__ float tile[64][65];
    int t = blockIdx.x;
    const float* Wt = W + (size_t)t * 4096;
    for (int idx = threadIdx.x; idx < 4096; idx += blockDim.x)
        tile[idx >> 6][idx & 63] = Wt[idx];
    __syncthreads();
    float* O = WT_g + (size_t)t * 4096;
    for (int idx = threadIdx.x; idx < 4096; idx += blockDim.x)
        O[idx] = tile[idx & 63][idx >> 6];   // stride-65 rows -> conflict-free
}

// ---------------- phase 0b: softplus table ----------------
__global__ void k_softplus(const float* __restrict__ ne) {
    int idx = blockIdx.x * blockDim.x + threadIdx.x;
    if (idx >= TT * NODE) return;
    int t = idx >> 6, j = idx & 63;
    float v;
    if (t == 0) v = 1.0f;                      // IN_SCALE at t=0
    else {
        float x = ne[j * TT + t];              // noise_embedding (1, NODE, T)
        v = fmaxf(x, 0.0f) + log1pf(expf(-fabsf(x)));
    }
    st_g[idx] = v;
}

__device__ __forceinline__ void cp_async16(uint32_t dst, const void* src) {
    asm volatile("cp.async.cg.shared.global [%0], [%1], 16;\n" :: "r"(dst), "l"(src));
}
__device__ __forceinline__ void fma2(unsigned long long& acc,
                                     unsigned long long a, unsigned long long b) {
    asm volatile("fma.rn.f32x2 %0, %1, %2, %0;" : "+l"(acc) : "l"(a), "l"(b));
}
__device__ __forceinline__ unsigned long long pack2(float lo, float hi) {
    unsigned long long r;
    asm("mov.b64 %0, {%1, %2};" : "=l"(r) : "r"(__float_as_uint(lo)), "r"(__float_as_uint(hi)));
    return r;
}
__device__ __forceinline__ float lo2(unsigned long long v) {
    unsigned int lo, hi;
    asm("mov.b64 {%0, %1}, %2;" : "=r"(lo), "=r"(hi) : "l"(v));
    return __uint_as_float(lo);
}
__device__ __forceinline__ float hi2(unsigned long long v) {
    unsigned int lo, hi;
    asm("mov.b64 {%0, %1}, %2;" : "=r"(lo), "=r"(hi) : "l"(v));
    return __uint_as_float(hi);
}

// ---------------- main: barrier-light fused recurrence ----------------
// Warp w owns rows {2w, 2w+1}. Lane: h = ln>>4 selects row, c = ln&15 selects
// 4 contiguous cols j = 4c..4c+3. x lives in registers; cross-lane x exchange
// via __shfl_sync. W[t] streams through an 8-slot smem ring; barrier only
// every 4 steps (issue next 4 / wait current 4 / publish).
__global__ void __launch_bounds__(NTHREADS, 1)
k_chain(const float* __restrict__ b,
        const float* __restrict__ eps0,
        const float* __restrict__ eps,
        float* __restrict__ out)
{
    extern __shared__ float ws[];   // NBUF * WBUF_FLOATS

    const int tid = threadIdx.x;
    const int w   = tid >> 5;
    const int ln  = tid & 31;
    const int h   = ln >> 4;            // row parity within warp
    const int c   = ln & 15;            // col group
    const int j0  = c << 2;             // first of 4 contiguous cols
    const int r   = 2 * w + h;          // 0..15
    const int m   = blockIdx.x * RB + r;

    float* __restrict__ outx = out;
    float* __restrict__ outm = out + (size_t)MM * NODE * TT;
    float* __restrict__ outs = out + 2 * (size_t)MM * NODE * TT;

    const uint32_t ws_base = (uint32_t)__cvta_generic_to_shared(ws);

    // Issue W[tp..tp+3] into ring slots (t & 7). Guarded past t=255.
    auto prefetch4 = [&](int tp) {
        #pragma unroll
        for (int q = 0; q < 4; ++q) {
            int tq = tp + q;
            if (tq <= 255) {
                const float* src = WT_g + (size_t)tq * WBUF_FLOATS;
                uint32_t dstb = ws_base + (uint32_t)(tq & (NBUF - 1)) * (WBUF_FLOATS * 4);
                #pragma unroll
                for (int i = 0; i < 4; ++i) {
                    int f = tid + i * NTHREADS;           // 0..1023 chunks of 16B
                    cp_async16(dstb + (uint32_t)f * 16u, src + f * 4);
                }
            }
        }
        asm volatile("cp.async.commit_group;\n");
    };

    prefetch4(1);   // group 0: W[1..4]

    // ---- t = 0 state ----
    float4 xv = *(const float4*)(eps0 + (size_t)m * NODE + j0);  // x0 = eps0 (s0=1)
    float xreg[4][4], mreg[4][4], sreg[4][4];
    #pragma unroll
    for (int i = 0; i < 4; ++i) {
        xreg[0][i] = ((const float*)&xv)[i];
        mreg[0][i] = 0.0f;
        sreg[0][i] = 1.0f;
    }

    // per-step vectors for t=1
    float4 bv = *(const float4*)(b + 64 + j0);
    float4 sv = *(const float4*)(st_g + 64 + j0);
    float4 ev = *(const float4*)(eps + (size_t)m * NODE + j0);

    int t = 1;
    while (t < TT) {
        // ---- phase boundary (every 4 steps) ----
        __syncthreads();                 // ring slots (t+4..t+7)&7 retired by all
        prefetch4(t + 4);                // fill them with W[t+4..t+7]
        asm volatile("cp.async.wait_group 1;\n");   // W[t..t+3] landed (this thread)
        __syncthreads();                 // publish to all threads

        #pragma unroll
        for (int q = 0; q < 4; ++q, ++t) {
            if (t >= TT) break;
            const float* wt = ws + (t & (NBUF - 1)) * WBUF_FLOATS + j0;

            // prefetch next-step vectors (hidden under fma block)
            float4 bn, sn, en;
            if (t + 1 < TT) {
                bn = *(const float4*)(b + (t + 1) * 64 + j0);
                sn = *(const float4*)(st_g + (t + 1) * 64 + j0);
                en = *(const float4*)(eps + ((size_t)t * MM + m) * NODE + j0);
            }

            // acc over j-pairs: accA=(m_j0,m_j1), accB=(m_j2,m_j3)
            unsigned long long accA = pack2(bv.x, bv.y);
            unsigned long long accB = pack2(bv.z, bv.w);

            #pragma unroll
            for (int kc = 0; kc < 16; ++kc) {
                const int src = (h << 4) + kc;   // lane holding x[r][4kc..4kc+3]
                float x0 = __shfl_sync(0xffffffffu, xv.x, src);
                float x1 = __shfl_sync(0xffffffffu, xv.y, src);
                float x2 = __shfl_sync(0xffffffffu, xv.z, src);
                float x3 = __shfl_sync(0xffffffffu, xv.w, src);
                float4 w0 = *(const float4*)(wt + (4 * kc + 0) * 64);  // 256B coalesced
                float4 w1 = *(const float4*)(wt + (4 * kc + 1) * 64);
                float4 w2 = *(const float4*)(wt + (4 * kc + 2) * 64);
                float4 w3 = *(const float4*)(wt + (4 * kc + 3) * 64);
                fma2(accA, pack2(x0, x0), pack2(w0.x, w0.y));
                fma2(accB, pack2(x0, x0), pack2(w0.z, w0.w));
                fma2(accA, pack2(x1, x1), pack2(w1.x, w1.y));
                fma2(accB, pack2(x1, x1), pack2(w1.z, w1.w));
                fma2(accA, pack2(x2, x2), pack2(w2.x, w2.y));
                fma2(accB, pack2(x2, x2), pack2(w2.z, w2.w));
                fma2(accA, pack2(x3, x3), pack2(w3.x, w3.y));
                fma2(accB, pack2(x3, x3), pack2(w3.z, w3.w));
            }

            float a0 = lo2(accA), a1 = hi2(accA), a2 = lo2(accB), a3 = hi2(accB);
            xv.x = fmaf(sv.x, ev.x, a0);
            xv.y = fmaf(sv.y, ev.y, a1);
            xv.z = fmaf(sv.z, ev.z, a2);
            xv.w = fmaf(sv.w, ev.w, a3);

            const int tl = t & 3;
            mreg[tl][0] = a0;  mreg[tl][1] = a1;  mreg[tl][2] = a2;  mreg[tl][3] = a3;
            xreg[tl][0] = xv.x; xreg[tl][1] = xv.y; xreg[tl][2] = xv.z; xreg[tl][3] = xv.w;
            sreg[tl][0] = sv.x; sreg[tl][1] = sv.y; sreg[tl][2] = sv.z; sreg[tl][3] = sv.w;

            bv = bn; sv = sn; ev = en;

            // ---- flush every 4 steps: reversed, 16B-aligned float4 ----
            if (tl == 3) {
                const int ch    = t >> 2;          // chunk 0..63 covers t=4ch..4ch+3
                const int obase = 252 - 4 * ch;    // out offset of t=4ch+3
                #pragma unroll
                for (int i = 0; i < 4; ++i) {
                    size_t base = ((size_t)m * NODE + j0 + i) * TT + obase;
                    *(float4*)(outx + base) = make_float4(xreg[3][i], xreg[2][i], xreg[1][i], xreg[0][i]);
                    *(float4*)(outm + base) = make_float4(mreg[3][i], mreg[2][i], mreg[1][i], mreg[0][i]);
                    *(float4*)(outs + base) = make_float4(sreg[3][i], sreg[2][i], sreg[1][i], sreg[0][i]);
                }
            }
        }
    }
}

extern "C" void kernel_launch(void* const* d_in, const int* in_sizes, int n_in,
                              void* d_out, int out_size) {
    const float* W    = (const float*)d_in[0];   // (T, NODE, NODE)
    const float* b    = (const float*)d_in[1];   // (T, NODE)
    const float* ne   = (const float*)d_in[2];   // (1, NODE, T)
    const float* eps0 = (const float*)d_in[3];   // (M, NODE)
    const float* eps  = (const float*)d_in[4];   // (T-1, M, NODE)
    float* out = (float*)d_out;                  // [x | m | s], each (M, NODE, T)

    // Idempotent attribute set (not a stream op; capture-safe)
    static_assert(NBUF * WBUF_FLOATS * 4 == 131072, "ring size");
    cudaFuncSetAttribute(k_chain, cudaFuncAttributeMaxDynamicSharedMemorySize, 131072);

    k_transpose_W<<<TT, 256>>>(W);
    k_softplus<<<(TT * NODE + 255) / 256, 256>>>(ne);
    k_chain<<<MM / RB, NTHREADS, 131072>>>(b, eps0, eps, out);
}

// round 11
// speedup vs baseline: 1.4167x; 1.4167x over previous
#include <cuda_runtime.h>
#include <cstdint>

#define MM 2048
#define NODE 64
#define TT 256
#define RB 16
#define NTHREADS 256
#define XROW 68            // xs row stride in floats (272B): conflict-free x loads

// Scratch (no cudaMalloc allowed): transposed weights (k-major) + softplus table
__device__ __align__(16) float WT_g[TT * NODE * NODE];   // 4 MB
__device__ __align__(16) float st_g[TT * NODE];          // 64 KB, st_g[0][:]=1.0

// ---------------- phase 0a: W[t][j][k] -> WT[t][k][j] ----------------
__global__ void k_transpose_W(const float* __restrict__ W) {
    __shared__ float tile[64][65];
    int t = blockIdx.x;
    const float* Wt = W + (size_t)t * 4096;
    for (int idx = threadIdx.x; idx < 4096; idx += blockDim.x)
        tile[idx >> 6][idx & 63] = Wt[idx];
    __syncthreads();
    float* O = WT_g + (size_t)t * 4096;
    for (int idx = threadIdx.x; idx < 4096; idx += blockDim.x)
        O[idx] = tile[idx & 63][idx >> 6];   // stride-65 rows -> conflict-free
}

// ---------------- phase 0b: softplus table ----------------
__global__ void k_softplus(const float* __restrict__ ne) {
    int idx = blockIdx.x * blockDim.x + threadIdx.x;
    if (idx >= TT * NODE) return;
    int t = idx >> 6, j = idx & 63;
    float v;
    if (t == 0) v = 1.0f;                       // IN_SCALE at t=0
    else {
        float x = ne[j * TT + t];               // noise_embedding (1, NODE, T)
        v = fmaxf(x, 0.0f) + log1pf(expf(-fabsf(x)));
    }
    st_g[idx] = v;
}

__device__ __forceinline__ void cp_async16(uint32_t dst, const void* src) {
    asm volatile("cp.async.cg.shared.global [%0], [%1], 16;\n" :: "r"(dst), "l"(src));
}

// ---------------- main: fused 255-step recurrence ----------------
// Warp shape: 8 rows x 4 col-groups. W LDS.128 -> 4 distinct addrs (64B,
// 1 wavefront, 8x broadcast). x LDS.128 -> 8 distinct rows (128B, 1 wavefront,
// 4x broadcast). Scalar FFMA core (no packing movs). W double-buffered via
// cp.async; per-step vectors prefetched one step ahead.
__global__ void __launch_bounds__(NTHREADS, 1)
k_chain(const float* __restrict__ b,
        const float* __restrict__ eps0,
        const float* __restrict__ eps,
        float* __restrict__ out)
{
    // W double buffer: Wsh[buf][k][j] (64 floats per k-row, unpadded) — 32 KB
    __shared__ float4 Wsh[2][NODE][NODE / 4];
    // x double buffer, rows padded to 272B
    __shared__ float xs[2][RB * XROW];

    const int tid = threadIdx.x;
    const int w   = tid >> 5;             // 0..7
    const int ln  = tid & 31;
    const int rl  = ln >> 2;              // 0..7 : row within warp
    const int gl  = ln & 3;               // 0..3 : col-group within warp
    const int r   = (w & 1) * 8 + rl;     // 0..15 : row within CTA tile
    const int cg  = (w >> 1) * 4 + gl;    // 0..15 : col group (4 cols)
    const int j0  = cg << 2;
    const int m   = blockIdx.x * RB + r;

    float* __restrict__ outx = out;
    float* __restrict__ outm = out + (size_t)MM * NODE * TT;
    float* __restrict__ outs = out + 2 * (size_t)MM * NODE * TT;

    const uint32_t wsh_base = (uint32_t)__cvta_generic_to_shared(&Wsh[0][0][0]);

    // Prefetch W[1] into buffer 1 (buffer parity == t&1); linear 16KB copy.
    {
        const float* src = WT_g + 4096;
        #pragma unroll
        for (int i = 0; i < 4; i++) {
            int f = tid + i * 256;
            cp_async16(wsh_base + 16384u + (uint32_t)f * 16u, src + f * 4);
        }
        asm volatile("cp.async.commit_group;\n");
    }

    float xreg[8][4], mreg[8][4];   // 8-step output staging (registers)

    // ---- t = 0: x0 = eps0, m0 = 0 ----
    {
        float4 e0 = *(const float4*)(eps0 + (size_t)m * NODE + j0);
        xreg[0][0] = e0.x; xreg[0][1] = e0.y; xreg[0][2] = e0.z; xreg[0][3] = e0.w;
        mreg[0][0] = 0.f;  mreg[0][1] = 0.f;  mreg[0][2] = 0.f;  mreg[0][3] = 0.f;
        *(float4*)&xs[0][r * XROW + j0] = e0;
    }

    // Prefetch per-step vectors for t=1 (registers)
    float4 bv = *(const float4*)(b + 64 + j0);
    float4 sv = *(const float4*)(st_g + 64 + j0);
    float4 ev = __ldcs((const float4*)(eps + (size_t)m * NODE + j0));

    #pragma unroll 1
    for (int t = 1; t < TT; ++t) {
        const int cur = (t - 1) & 1;
        const int nxt = t & 1;

        // 1) W[t] landed. 2) Barrier: retired buffer free, xs[cur] visible.
        asm volatile("cp.async.wait_group 0;\n");
        __syncthreads();
        // 3) Prefetch W[t+1] into retired buffer (overlaps FFMA block).
        if (t + 1 < TT) {
            const float* src = WT_g + (size_t)(t + 1) * 4096;
            uint32_t dstb = wsh_base + (uint32_t)((t + 1) & 1) * 16384u;
            #pragma unroll
            for (int i = 0; i < 4; i++) {
                int f = tid + i * 256;
                cp_async16(dstb + (uint32_t)f * 16u, src + f * 4);
            }
            asm volatile("cp.async.commit_group;\n");
        }

        // Prefetch per-step vectors for t+1 (hidden under FFMA block)
        const int tp = (t + 1 < TT) ? (t + 1) : t;
        float4 bn = *(const float4*)(b + tp * 64 + j0);
        float4 sn = *(const float4*)(st_g + tp * 64 + j0);
        float4 en = __ldcs((const float4*)(eps + ((size_t)(tp - 1) * MM + m) * NODE + j0));

        float a0 = bv.x, a1 = bv.y, a2 = bv.z, a3 = bv.w;

        const float* xrow = &xs[cur][r * XROW];
        const float4* wcol = &Wsh[nxt][0][cg];   // lane gl -> 4 distinct 16B, 8x bcast

        #pragma unroll
        for (int kc = 0; kc < 16; ++kc) {
            float4 xv = *(const float4*)(xrow + kc * 4);   // 8 rows x 16B = 128B, 1 wf
            float4 w0 = wcol[(4 * kc + 0) * 16];           // 4 x 16B = 64B, 1 wf
            float4 w1 = wcol[(4 * kc + 1) * 16];
            float4 w2 = wcol[(4 * kc + 2) * 16];
            float4 w3 = wcol[(4 * kc + 3) * 16];
            a0 += xv.x * w0.x; a1 += xv.x * w0.y; a2 += xv.x * w0.z; a3 += xv.x * w0.w;
            a0 += xv.y * w1.x; a1 += xv.y * w1.y; a2 += xv.y * w1.z; a3 += xv.y * w1.w;
            a0 += xv.z * w2.x; a1 += xv.z * w2.y; a2 += xv.z * w2.z; a3 += xv.z * w2.w;
            a0 += xv.w * w3.x; a1 += xv.w * w3.y; a2 += xv.w * w3.z; a3 += xv.w * w3.w;
        }

        float x0 = a0 + sv.x * ev.x;
        float x1 = a1 + sv.y * ev.y;
        float x2 = a2 + sv.z * ev.z;
        float x3 = a3 + sv.w * ev.w;

        const int tl = t & 7;
        mreg[tl][0] = a0; mreg[tl][1] = a1; mreg[tl][2] = a2; mreg[tl][3] = a3;
        xreg[tl][0] = x0; xreg[tl][1] = x1; xreg[tl][2] = x2; xreg[tl][3] = x3;

        *(float4*)&xs[nxt][r * XROW + j0] = make_float4(x0, x1, x2, x3);

        bv = bn; sv = sn; ev = en;

        // ---- flush every 8 steps: reversed, 32B-aligned float4 pairs ----
        if (tl == 7) {
            const int cch   = t >> 3;            // chunk id, 0..31
            const int obase = 248 - 8 * cch;     // out offset of t = 8c+7 .. 8c
            float sreg[8][4];
            #pragma unroll
            for (int u = 0; u < 8; ++u) {
                float4 s4 = *(const float4*)(st_g + (8 * cch + u) * NODE + j0);
                sreg[u][0] = s4.x; sreg[u][1] = s4.y; sreg[u][2] = s4.z; sreg[u][3] = s4.w;
            }
            #pragma unroll
            for (int i = 0; i < 4; ++i) {
                size_t base = ((size_t)m * NODE + j0 + i) * TT + obase;
                __stcs((float4*)(outx + base),     make_float4(xreg[7][i], xreg[6][i], xreg[5][i], xreg[4][i]));
                __stcs((float4*)(outx + base + 4), make_float4(xreg[3][i], xreg[2][i], xreg[1][i], xreg[0][i]));
                __stcs((float4*)(outm + base),     make_float4(mreg[7][i], mreg[6][i], mreg[5][i], mreg[4][i]));
                __stcs((float4*)(outm + base + 4), make_float4(mreg[3][i], mreg[2][i], mreg[1][i], mreg[0][i]));
                __stcs((float4*)(outs + base),     make_float4(sreg[7][i], sreg[6][i], sreg[5][i], sreg[4][i]));
                __stcs((float4*)(outs + base + 4), make_float4(sreg[3][i], sreg[2][i], sreg[1][i], sreg[0][i]));
            }
        }
    }
}

extern "C" void kernel_launch(void* const* d_in, const int* in_sizes, int n_in,
                              void* d_out, int out_size) {
    const float* W    = (const float*)d_in[0];   // (T, NODE, NODE)
    const float* b    = (const float*)d_in[1];   // (T, NODE)
    const float* ne   = (const float*)d_in[2];   // (1, NODE, T)
    const float* eps0 = (const float*)d_in[3];   // (M, NODE)
    const float* eps  = (const float*)d_in[4];   // (T-1, M, NODE)
    float* out = (float*)d_out;                  // [x | m | s], each (M, NODE, T)

    k_transpose_W<<<TT, 256>>>(W);
    k_softplus<<<(TT * NODE + 255) / 256, 256>>>(ne);
    k_chain<<<MM / RB, NTHREADS>>>(b, eps0, eps, out);
}